// round 11
// baseline (speedup 1.0000x reference)
#include <cuda_runtime.h>

// Problem constants: B=256, T=2048, I=2, H=128, 3H=384
#define BB 256
#define TT 2048
#define HH 128
#define NTHREADS 512

__device__ int d_order[BB];

// Plain descending-length order (R2-proven best): wave 1 = 148 longest,
// wave-2 CTAs work-stolen in bid order = LPT.
__global__ void order_kernel(const int* __restrict__ lengths) {
    int i = threadIdx.x;
    int li = lengths[i];
    int rank = 0;
    #pragma unroll 8
    for (int j = 0; j < BB; j++) {
        int lj = lengths[j];
        rank += (lj > li) || (lj == li && j < i);
    }
    d_order[rank] = i;
}

// ---- packed f32x2 helpers ----
__device__ __forceinline__ unsigned long long fma2(unsigned long long a,
                                                   unsigned long long b,
                                                   unsigned long long c) {
    unsigned long long d;
    asm("fma.rn.f32x2 %0, %1, %2, %3;" : "=l"(d) : "l"(a), "l"(b), "l"(c));
    return d;
}
__device__ __forceinline__ unsigned long long pack2(float x, float y) {
    unsigned long long r;
    asm("mov.b64 %0, {%1, %2};" : "=l"(r) : "f"(x), "f"(y));
    return r;
}
__device__ __forceinline__ void unpack2(unsigned long long v, float& x, float& y) {
    asm("mov.b64 {%0, %1}, %2;" : "=f"(x), "=f"(y) : "l"(v));
}
__device__ __forceinline__ float tanh_fast(float v) {
    float r;
    asm("tanh.approx.f32 %0, %1;" : "=f"(r) : "f"(v));
    return r;
}

// NIBBLE design: 512 threads, 16 warps, 4 lanes per hidden index j.
//   warp w owns j in [8w, 8w+8); lane L handles j = 8w + (L>>2), sub = L&3.
//   sub s owns h-columns [32s, 32s+32) of ALL THREE rows (r_j, z_j, n_j):
//   one 32-float h chunk loaded once (8 LDS.128) feeds 3 x 16 FMA2 chains.
//   Gate partial sums are reduced intra-warp with shfl.xor(1), shfl.xor(2)
//   (nibble-local), so EVERY lane gets (gr,gz,gn) -> gate math is uniform
//   (no divergence/BSSY); sub0 stores h with a single predicated STS.
//   ONE __syncthreads per step (h ping-pong makes it sufficient).
__global__ void __launch_bounds__(NTHREADS, 1)
gru_kernel(const float* __restrict__ x,        // [B, T, 2]
           const int*   __restrict__ lengths,  // [B]
           const float* __restrict__ W_ih,     // [384, 2]
           const float* __restrict__ W_hh,     // [384, 128]
           const float* __restrict__ b_ih,     // [384]
           const float* __restrict__ b_hh,     // [384]
           const float* __restrict__ head_w,   // [128]
           const float* __restrict__ head_b,   // [1]
           float*       __restrict__ out)      // [B, 1]
{
    __shared__ __align__(16) float sh_x[TT * 2 + 4];  // input seq + pad
    __shared__ __align__(16) float sh_h[2][HH];       // ping-pong hidden state
    __shared__ float sh_red[4];

    const int tid = threadIdx.x;
    const int b = d_order[blockIdx.x];
    const int len = lengths[b];

    const int lane = tid & 31;
    const int sub = lane & 3;
    const int j = ((tid >> 5) << 3) + (lane >> 2);   // 8*warp + nibble

    // --- load input prefix into shared ---
    {
        const float4* xs = reinterpret_cast<const float4*>(x + (size_t)b * (TT * 2));
        float4* xd = reinterpret_cast<float4*>(sh_x);
        int nq = (len * 2 + 3) >> 2;
        for (int q = tid; q < nq; q += NTHREADS) xd[q] = xs[q];
        if (tid < 4) sh_x[TT * 2 + tid] = 0.0f;
    }

    // --- weights: columns [32*sub, 32*sub+32) of rows j, 128+j, 256+j ---
    unsigned long long wr[16], wz[16], wn[16];
    {
        const unsigned long long* pr = reinterpret_cast<const unsigned long long*>(
            W_hh + (size_t)j * HH + 32 * sub);
        const unsigned long long* pz = reinterpret_cast<const unsigned long long*>(
            W_hh + (size_t)(HH + j) * HH + 32 * sub);
        const unsigned long long* pn = reinterpret_cast<const unsigned long long*>(
            W_hh + (size_t)(2 * HH + j) * HH + 32 * sub);
        #pragma unroll
        for (int k = 0; k < 16; k++) { wr[k] = pr[k]; wz[k] = pz[k]; wn[k] = pn[k]; }
    }

    // b_hh folded into sub0's accumulator init (added exactly once per gate).
    const float bfr = (sub == 0) ? b_hh[j] : 0.0f;
    const float bfz = (sub == 0) ? b_hh[HH + j] : 0.0f;
    const float bfn = (sub == 0) ? b_hh[2 * HH + j] : 0.0f;

    // Input-projection constants (same j across the nibble -> identical values
    // on all 4 lanes; gate math is executed uniformly). sigma prescale folded.
    float rw0, rw1, rb, zw0, zw1, zb, nw0, nw1, nb;
    {
        float2 t2 = *reinterpret_cast<const float2*>(W_ih + (size_t)j * 2);
        rw0 = 0.5f * t2.x; rw1 = 0.5f * t2.y; rb = 0.5f * b_ih[j];
        t2 = *reinterpret_cast<const float2*>(W_ih + (size_t)(HH + j) * 2);
        zw0 = 0.5f * t2.x; zw1 = 0.5f * t2.y; zb = 0.5f * b_ih[HH + j];
        t2 = *reinterpret_cast<const float2*>(W_ih + (size_t)(2 * HH + j) * 2);
        nw0 = t2.x; nw1 = t2.y; nb = b_ih[2 * HH + j];
    }
    float h = 0.0f;
    if (tid < HH) sh_h[0][tid] = 0.0f;
    __syncthreads();

    int cur = 0;
    for (int t = 0; t < len; t++) {
        // x projections (broadcast LDS.64; needed only ~400 cyc later).
        float2 xt = *reinterpret_cast<const float2*>(sh_x + 2 * t);
        float xr2 = fmaf(rw0, xt.x, fmaf(rw1, xt.y, rb));
        float xz2 = fmaf(zw0, xt.x, fmaf(zw1, xt.y, zb));
        float xn  = fmaf(nw0, xt.x, fmaf(nw1, xt.y, nb));

        // Matvec partials over own 32-column chunk; h chunk loaded ONCE,
        // reused by all 3 gate rows. 3 chains, same-chain ops 3 slots apart.
        unsigned long long aR = pack2(bfr, 0.0f);
        unsigned long long aZ = pack2(bfz, 0.0f);
        unsigned long long aN = pack2(bfn, 0.0f);
        const ulonglong2* hseg =
            reinterpret_cast<const ulonglong2*>(sh_h[cur] + 32 * sub);
        #pragma unroll
        for (int k = 0; k < 8; k++) {
            ulonglong2 hv = hseg[k];            // LDS.128 (4 h values)
            aR = fma2(wr[2 * k],     hv.x, aR);
            aZ = fma2(wz[2 * k],     hv.x, aZ);
            aN = fma2(wn[2 * k],     hv.x, aN);
            aR = fma2(wr[2 * k + 1], hv.y, aR);
            aZ = fma2(wz[2 * k + 1], hv.y, aZ);
            aN = fma2(wn[2 * k + 1], hv.y, aN);
        }
        float rx, ry, zx, zy, nx, ny;
        unpack2(aR, rx, ry);
        unpack2(aZ, zx, zy);
        unpack2(aN, nx, ny);
        float pr = rx + ry, pz = zx + zy, pn = nx + ny;

        // Nibble reduction: after xor1+xor2 every lane holds full sums.
        pr += __shfl_xor_sync(0xffffffffu, pr, 1);
        pz += __shfl_xor_sync(0xffffffffu, pz, 1);
        pn += __shfl_xor_sync(0xffffffffu, pn, 1);
        pr += __shfl_xor_sync(0xffffffffu, pr, 2);
        pz += __shfl_xor_sync(0xffffffffu, pz, 2);
        pn += __shfl_xor_sync(0xffffffffu, pn, 2);

        // Gates (uniform on all lanes; only sub0's h is stored).
        float r_t = tanh_fast(fmaf(0.5f, pr, xr2));
        float z_t = tanh_fast(fmaf(0.5f, pz, xz2));
        float gnh = 0.5f * pn;
        float n = tanh_fast(fmaf(r_t, gnh, xn + gnh));   // tanh(xn + r*gn)
        h = 0.5f * fmaf(z_t, h - n, h + n);              // (1-z)*n + z*h
        if (sub == 0) sh_h[cur ^ 1][j] = h;              // predicated STS
        __syncthreads();
        cur ^= 1;
    }

    // --- head: out[b] = sum_j h[j]*head_w[j] + head_b ---
    if (tid < HH) {
        float v = sh_h[cur][tid] * head_w[tid];
        #pragma unroll
        for (int o = 16; o > 0; o >>= 1) v += __shfl_down_sync(0xffffffffu, v, o);
        if ((tid & 31) == 0) sh_red[tid >> 5] = v;
    }
    __syncthreads();
    if (tid == 0) {
        out[b] = (sh_red[0] + sh_red[1]) + (sh_red[2] + sh_red[3]) + head_b[0];
    }
}

extern "C" void kernel_launch(void* const* d_in, const int* in_sizes, int n_in,
                              void* d_out, int out_size) {
    const float* x      = (const float*)d_in[0];
    const int*   len    = (const int*)  d_in[1];
    const float* W_ih   = (const float*)d_in[2];
    const float* W_hh   = (const float*)d_in[3];
    const float* b_ih   = (const float*)d_in[4];
    const float* b_hh   = (const float*)d_in[5];
    const float* head_w = (const float*)d_in[6];
    const float* head_b = (const float*)d_in[7];
    float* out = (float*)d_out;

    order_kernel<<<1, BB>>>(len);
    gru_kernel<<<BB, NTHREADS>>>(x, len, W_ih, W_hh, b_ih, b_hh,
                                 head_w, head_b, out);
}

// round 12
// speedup vs baseline: 2.8795x; 2.8795x over previous
#include <cuda_runtime.h>

// Problem constants: B=256, T=2048, I=2, H=128, 3H=384
#define BB 256
#define TT 2048
#define HH 128
#define NTHREADS 256

__device__ int d_order[BB];

// Plain descending-length order (R2-proven best): wave 1 = 148 longest,
// wave-2 CTAs work-stolen in bid order = LPT.
__global__ void order_kernel(const int* __restrict__ lengths) {
    int i = threadIdx.x;
    int li = lengths[i];
    int rank = 0;
    #pragma unroll 8
    for (int j = 0; j < BB; j++) {
        int lj = lengths[j];
        rank += (lj > li) || (lj == li && j < i);
    }
    d_order[rank] = i;
}

// ---- packed f32x2 helpers ----
__device__ __forceinline__ unsigned long long fma2(unsigned long long a,
                                                   unsigned long long b,
                                                   unsigned long long c) {
    unsigned long long d;
    asm("fma.rn.f32x2 %0, %1, %2, %3;" : "=l"(d) : "l"(a), "l"(b), "l"(c));
    return d;
}
__device__ __forceinline__ unsigned long long add2(unsigned long long a,
                                                   unsigned long long b) {
    unsigned long long d;
    asm("add.rn.f32x2 %0, %1, %2;" : "=l"(d) : "l"(a), "l"(b));
    return d;
}
__device__ __forceinline__ unsigned long long pack2(float x, float y) {
    unsigned long long r;
    asm("mov.b64 %0, {%1, %2};" : "=l"(r) : "f"(x), "f"(y));
    return r;
}
__device__ __forceinline__ void unpack2(unsigned long long v, float& x, float& y) {
    asm("mov.b64 {%0, %1}, %2;" : "=f"(x), "=f"(y) : "l"(v));
}
__device__ __forceinline__ float tanh_fast(float v) {
    float r;
    asm("tanh.approx.f32 %0, %1;" : "=f"(r) : "f"(v));
    return r;
}

// TRI-ROW HALF-COLUMN design: 256 threads, 8 warps.
//   tid = 128*half + j. Thread owns h-columns [64*half, 64*half+64) of ALL
//   THREE rows (r_j, z_j, n_j): the 64-float h chunk is loaded ONCE
//   (16 LDS.128) and reused by 3 gate rows -> LDS/SM/step drops 384 -> 128
//   (the smem crossbar was co-saturated with the FMA pipe in all previous
//   designs). FMA2 floor unchanged: 2 warps/SMSP x 96 x rt2 = 384 cyc.
//   Exchange: upper half STS.128 {pr,pz,pn}; pair barrier (warps w, w+4 =
//   same SMSP, 64 threads); lower half sums, computes gates, stores h; one
//   full __syncthreads publishes h (ping-pong).
__global__ void __launch_bounds__(NTHREADS, 1)
gru_kernel(const float* __restrict__ x,        // [B, T, 2]
           const int*   __restrict__ lengths,  // [B]
           const float* __restrict__ W_ih,     // [384, 2]
           const float* __restrict__ W_hh,     // [384, 128]
           const float* __restrict__ b_ih,     // [384]
           const float* __restrict__ b_hh,     // [384]
           const float* __restrict__ head_w,   // [128]
           const float* __restrict__ head_b,   // [1]
           float*       __restrict__ out)      // [B, 1]
{
    __shared__ __align__(16) float sh_x[TT * 2 + 4];  // input seq + pad
    __shared__ __align__(16) float sh_h[2][HH];       // ping-pong hidden state
    __shared__ __align__(16) float4 sh_p[HH];         // upper-half partials
    __shared__ float sh_red[4];

    const int tid = threadIdx.x;
    const int b = d_order[blockIdx.x];
    const int len = lengths[b];

    const int half = tid >> 7;            // 0 = lower/combiner, 1 = upper
    const int j = tid & 127;
    const int bar_id = 1 + ((tid >> 5) & 3);

    // --- load input prefix into shared ---
    {
        const float4* xs = reinterpret_cast<const float4*>(x + (size_t)b * (TT * 2));
        float4* xd = reinterpret_cast<float4*>(sh_x);
        int nq = (len * 2 + 3) >> 2;
        for (int q = tid; q < nq; q += NTHREADS) xd[q] = xs[q];
        if (tid < 4) sh_x[TT * 2 + tid] = 0.0f;
    }

    // --- weights: own 64-column half of rows j, 128+j, 256+j ---
    unsigned long long wr[32], wz[32], wn[32];
    {
        const size_t coff = 64 * half;
        const unsigned long long* pr = reinterpret_cast<const unsigned long long*>(
            W_hh + (size_t)j * HH + coff);
        const unsigned long long* pz = reinterpret_cast<const unsigned long long*>(
            W_hh + (size_t)(HH + j) * HH + coff);
        const unsigned long long* pn = reinterpret_cast<const unsigned long long*>(
            W_hh + (size_t)(2 * HH + j) * HH + coff);
        #pragma unroll
        for (int k = 0; k < 32; k++) { wr[k] = pr[k]; wz[k] = pz[k]; wn[k] = pn[k]; }
    }

    // Biases folded into the LOWER half's accumulators (added exactly once).
    const unsigned long long bR2 = pack2(half ? 0.0f : b_hh[j], 0.0f);
    const unsigned long long bZ2 = pack2(half ? 0.0f : b_hh[HH + j], 0.0f);
    const unsigned long long bN2 = pack2(half ? 0.0f : b_hh[2 * HH + j], 0.0f);
    const unsigned long long zero2 = pack2(0.0f, 0.0f);

    // Input-projection constants (lower half only; zeros on upper ->
    // branch-free straight-line x-proj, R4/R6-proven shape). sigma prescale
    // (0.5) folded into r and z.
    float rw0 = 0.f, rw1 = 0.f, rb = 0.f;
    float zw0 = 0.f, zw1 = 0.f, zb = 0.f;
    float nw0 = 0.f, nw1 = 0.f, nb = 0.f, hw = 0.f;
    float h = 0.0f;
    if (!half) {
        float2 t2 = *reinterpret_cast<const float2*>(W_ih + (size_t)j * 2);
        rw0 = 0.5f * t2.x; rw1 = 0.5f * t2.y; rb = 0.5f * b_ih[j];
        t2 = *reinterpret_cast<const float2*>(W_ih + (size_t)(HH + j) * 2);
        zw0 = 0.5f * t2.x; zw1 = 0.5f * t2.y; zb = 0.5f * b_ih[HH + j];
        t2 = *reinterpret_cast<const float2*>(W_ih + (size_t)(2 * HH + j) * 2);
        nw0 = t2.x; nw1 = t2.y; nb = b_ih[2 * HH + j];
        hw = head_w[j];
        sh_h[0][j] = 0.0f;
    }
    __syncthreads();

    int cur = 0;
    for (int t = 0; t < len; t++) {
        // x projections (broadcast LDS.64; h-independent, off critical path).
        float2 xt = *reinterpret_cast<const float2*>(sh_x + 2 * t);
        float xr2 = fmaf(rw0, xt.x, fmaf(rw1, xt.y, rb));
        float xz2 = fmaf(zw0, xt.x, fmaf(zw1, xt.y, zb));
        float xn  = fmaf(nw0, xt.x, fmaf(nw1, xt.y, nb));

        // Matvec over own 64-col half: h chunk loaded once, reused x3.
        // 6 independent FMA2 chains (same-chain reuse distance = 6 ops).
        unsigned long long aR0 = bR2, aR1 = zero2;
        unsigned long long aZ0 = bZ2, aZ1 = zero2;
        unsigned long long aN0 = bN2, aN1 = zero2;
        const ulonglong2* hseg =
            reinterpret_cast<const ulonglong2*>(sh_h[cur] + 64 * half);
        #pragma unroll
        for (int k = 0; k < 16; k++) {
            ulonglong2 hv = hseg[k];            // LDS.128 (4 h values)
            aR0 = fma2(wr[2 * k],     hv.x, aR0);
            aZ0 = fma2(wz[2 * k],     hv.x, aZ0);
            aN0 = fma2(wn[2 * k],     hv.x, aN0);
            aR1 = fma2(wr[2 * k + 1], hv.y, aR1);
            aZ1 = fma2(wz[2 * k + 1], hv.y, aZ1);
            aN1 = fma2(wn[2 * k + 1], hv.y, aN1);
        }
        unsigned long long sR = add2(aR0, aR1);
        unsigned long long sZ = add2(aZ0, aZ1);
        unsigned long long sN = add2(aN0, aN1);
        float ra, rbv, za, zbv, na, nbv;
        unpack2(sR, ra, rbv);
        unpack2(sZ, za, zbv);
        unpack2(sN, na, nbv);
        float pr = ra + rbv, pz = za + zbv, pn = na + nbv;

        if (half) {
            // Publish partials, arrive, and wait for h at the full barrier.
            sh_p[j] = make_float4(pr, pz, pn, 0.0f);
            asm volatile("bar.arrive %0, 64;" :: "r"(bar_id) : "memory");
            __syncthreads();
        } else {
            asm volatile("bar.sync %0, 64;" :: "r"(bar_id) : "memory");
            float4 p = sh_p[j];
            float gr = pr + p.x;
            float gz = pz + p.y;
            float gn = pn + p.z;
            float r_t = tanh_fast(fmaf(0.5f, gr, xr2));
            float z_t = tanh_fast(fmaf(0.5f, gz, xz2));
            float gnh = 0.5f * gn;
            float n = tanh_fast(fmaf(r_t, gnh, xn + gnh));  // tanh(xn + r*gn)
            h = 0.5f * fmaf(z_t, h - n, h + n);             // (1-z)*n + z*h
            sh_h[cur ^ 1][j] = h;
            __syncthreads();
        }
        cur ^= 1;
    }

    // --- head: out[b] = sum_j h[j]*head_w[j] + head_b (lower half holds h) ---
    if (!half) {
        float v = h * hw;
        #pragma unroll
        for (int o = 16; o > 0; o >>= 1) v += __shfl_down_sync(0xffffffffu, v, o);
        if ((tid & 31) == 0) sh_red[tid >> 5] = v;
    }
    __syncthreads();
    if (tid == 0) {
        out[b] = (sh_red[0] + sh_red[1]) + (sh_red[2] + sh_red[3]) + head_b[0];
    }
}

extern "C" void kernel_launch(void* const* d_in, const int* in_sizes, int n_in,
                              void* d_out, int out_size) {
    const float* x      = (const float*)d_in[0];
    const int*   len    = (const int*)  d_in[1];
    const float* W_ih   = (const float*)d_in[2];
    const float* W_hh   = (const float*)d_in[3];
    const float* b_ih   = (const float*)d_in[4];
    const float* b_hh   = (const float*)d_in[5];
    const float* head_w = (const float*)d_in[6];
    const float* head_b = (const float*)d_in[7];
    float* out = (float*)d_out;

    order_kernel<<<1, BB>>>(len);
    gru_kernel<<<BB, NTHREADS>>>(x, len, W_ih, W_hh, b_ih, b_hh,
                                 head_w, head_b, out);
}